// round 12
// baseline (speedup 1.0000x reference)
#include <cuda_runtime.h>
#include <cuda_fp16.h>
#include <cstdint>
#include <cstddef>

#define DI __device__ __forceinline__
constexpr int NB = 8, C = 512, NP = 4096;

__device__ __align__(1024) __half gH[(size_t)NB * NP * C];
__device__ __align__(1024) __half gQ[(size_t)NB * NP * C];
__device__ __align__(1024) __half gK[(size_t)NB * NP * C];
__device__ __align__(1024) __half gVt[(size_t)NB * C * NP];
__device__ __align__(1024) __half gO[(size_t)NB * NP * C];
__device__ __align__(1024) __half gS[(size_t)NB * NP * NP];
__device__ __align__(1024) __half gW[4 * 512 * 512];
__device__ float gStat[NB * 32 * 2];

DI uint32_t su32(const void* p) { return (uint32_t)__cvta_generic_to_shared(p); }
DI void cp16(void* s, const void* g) {
    asm volatile("cp.async.cg.shared.global [%0], [%1], 16;\n" ::"r"(su32(s)), "l"(g) : "memory");
}
DI void cpc() { asm volatile("cp.async.commit_group;\n" ::: "memory"); }
DI void ldsm4(uint32_t* r, uint32_t a) {
    asm volatile("ldmatrix.sync.aligned.m8n8.x4.shared.b16 {%0,%1,%2,%3}, [%4];\n"
                 : "=r"(r[0]), "=r"(r[1]), "=r"(r[2]), "=r"(r[3]) : "r"(a));
}
DI void mma(float* d, const uint32_t* a, uint32_t b0, uint32_t b1) {
    asm volatile("mma.sync.aligned.m16n8k16.row.col.f32.f16.f16.f32 "
                 "{%0,%1,%2,%3}, {%4,%5,%6,%7}, {%8,%9}, {%0,%1,%2,%3};\n"
                 : "+f"(d[0]), "+f"(d[1]), "+f"(d[2]), "+f"(d[3])
                 : "r"(a[0]), "r"(a[1]), "r"(a[2]), "r"(a[3]), "r"(b0), "r"(b1));
}

__global__ void gn_stats(const float* __restrict__ x) {
    const int g = blockIdx.x, b = blockIdx.y, t = threadIdx.x;
    const float4* xp = (const float4*)(x + ((size_t)b * C + g * 16) * NP);
    float s = 0.f, s2 = 0.f;
    for (int i = t; i < 16 * NP / 4; i += 256) {
        float4 v = xp[i];
        s += v.x + v.y + v.z + v.w;
        s2 += v.x * v.x + v.y * v.y + v.z * v.z + v.w * v.w;
    }
    __shared__ float rs[8], rs2[8];
#pragma unroll
    for (int o = 16; o; o >>= 1) {
        s += __shfl_xor_sync(~0u, s, o);
        s2 += __shfl_xor_sync(~0u, s2, o);
    }
    if ((t & 31) == 0) { rs[t >> 5] = s; rs2[t >> 5] = s2; }
    __syncthreads();
    if (t == 0) {
        float a = 0.f, a2 = 0.f;
        for (int i = 0; i < 8; i++) { a += rs[i]; a2 += rs2[i]; }
        const float inv = 1.f / (16.f * NP);
        float m = a * inv, var = a2 * inv - m * m;
        gStat[(b * 32 + g) * 2] = m;
        gStat[(b * 32 + g) * 2 + 1] = rsqrtf(var + 1e-6f);
    }
}

__global__ void gn_apply(const float* __restrict__ x, const float* __restrict__ gw,
                         const float* __restrict__ gb) {
    extern __shared__ __half st[];  // [64 p][pitch 520 c]
    const int b = blockIdx.y, p0 = blockIdx.x * 64, t = threadIdx.x;
#pragma unroll 4
    for (int i = 0; i < 32; i++) {
        int id = i * 256 + t, c = id >> 4, p4 = (id & 15) * 4;
        float4 v = *(const float4*)(x + ((size_t)b * C + c) * NP + p0 + p4);
        int g = c >> 4;
        float rstd = gStat[(b * 32 + g) * 2 + 1], mean = gStat[(b * 32 + g) * 2];
        float sc = gw[c] * rstd, sh = gb[c] - mean * sc;
        st[(p4 + 0) * 520 + c] = __float2half(fmaf(v.x, sc, sh));
        st[(p4 + 1) * 520 + c] = __float2half(fmaf(v.y, sc, sh));
        st[(p4 + 2) * 520 + c] = __float2half(fmaf(v.z, sc, sh));
        st[(p4 + 3) * 520 + c] = __float2half(fmaf(v.w, sc, sh));
    }
    __syncthreads();
#pragma unroll 4
    for (int i = 0; i < 16; i++) {
        int id = i * 256 + t, p = id >> 6, cc = (id & 63) * 8;
        *(uint4*)(gH + ((size_t)b * NP + p0 + p) * C + cc) = *(uint4*)(st + p * 520 + cc);
    }
}

__global__ void wconv(const float* __restrict__ wq, const float* __restrict__ wk,
                      const float* __restrict__ wv, const float* __restrict__ wp) {
    const int i = blockIdx.x * 256 + threadIdx.x;
    gW[i] = __float2half(wq[i]);
    gW[262144 + i] = __float2half(wk[i]);
    gW[524288 + i] = __float2half(wv[i]);
    gW[786432 + i] = __float2half(wp[i]);
}

__global__ void softmax_k() {
    __half* rp = gS + (size_t)blockIdx.x * NP;
    const int t = threadIdx.x;
    __half2 h[16];
    uint4* up = (uint4*)rp;
#pragma unroll
    for (int i = 0; i < 4; i++) *(uint4*)&h[i * 4] = up[i * 128 + t];
    float mx = -1e30f;
#pragma unroll
    for (int i = 0; i < 16; i++) {
        float2 f = __half22float2(h[i]);
        mx = fmaxf(mx, fmaxf(f.x, f.y));
    }
    __shared__ float sh[4], sh2[4];
#pragma unroll
    for (int o = 16; o; o >>= 1) mx = fmaxf(mx, __shfl_xor_sync(~0u, mx, o));
    if ((t & 31) == 0) sh[t >> 5] = mx;
    __syncthreads();
    mx = fmaxf(fmaxf(sh[0], sh[1]), fmaxf(sh[2], sh[3]));
    float p[32], sum = 0.f;
#pragma unroll
    for (int i = 0; i < 16; i++) {
        float2 f = __half22float2(h[i]);
        p[2 * i] = exp2f((f.x - mx) * 1.44269504f);
        p[2 * i + 1] = exp2f((f.y - mx) * 1.44269504f);
        sum += p[2 * i] + p[2 * i + 1];
    }
#pragma unroll
    for (int o = 16; o; o >>= 1) sum += __shfl_xor_sync(~0u, sum, o);
    if ((t & 31) == 0) sh2[t >> 5] = sum;
    __syncthreads();
    float inv = 1.f / (sh2[0] + sh2[1] + sh2[2] + sh2[3]);
#pragma unroll
    for (int i = 0; i < 16; i++) h[i] = __floats2half2_rn(p[2 * i] * inv, p[2 * i + 1] * inv);
#pragma unroll
    for (int i = 0; i < 4; i++) up[i * 128 + t] = *(uint4*)&h[i * 4];
}

// C[m,n] = scale*(A[m,:].B[n,:]) + bias[n];  mode 0: fp16 [m,n]; 1: fp16 [n,m]; 2: fp32 [n,m]+res
// K-chunk 64 (128B swizzled rows), 3-stage cp.async ring, warp-parity k-step stagger,
// capped at 128 regs for 2 CTAs/SM. qkv!=0: fused Q/K/V launch, z = batch + 8*weightsel.
constexpr int STG = 3;
constexpr int STAGE_B = 32768;  // A 16KB + B 16KB
__global__ void __launch_bounds__(256, 2) gemm(
    const __half* __restrict__ A, const __half* __restrict__ B, size_t sA, size_t sB, int Kd,
    const float* __restrict__ bias, float scale, int mode, __half* __restrict__ Ho, size_t sHo,
    int ldo, const float* __restrict__ res, float* __restrict__ fo, int qkv,
    const float* __restrict__ biasK, const float* __restrict__ biasV, __half* __restrict__ HoK,
    __half* __restrict__ HoV) {
    extern __shared__ __align__(1024) char smc[];
    const int m0 = blockIdx.x * 128, n0 = blockIdx.y * 128;
    int z = blockIdx.z;
    if (qkv) {
        int ws = z >> 3;
        z &= 7;
        B += (size_t)ws * 262144;
        if (ws == 1) { bias = biasK; Ho = HoK; }
        else if (ws == 2) { bias = biasV; Ho = HoV; mode = 1; ldo = NP; }
    }
    const int t = threadIdx.x, w = t >> 5, l = t & 31;
    const int mi = w >> 2, ni = w & 3;
    A += (size_t)z * sA;
    B += (size_t)z * sB;
    const int nc = Kd >> 6;
    float acc[4][4][4] = {};
    auto load = [&](int s, int kc) {
        char* Ab = smc + s * STAGE_B;
        char* Bb = Ab + 16384;
#pragma unroll
        for (int j = 0; j < 4; j++) {
            int id = t + j * 256, r = id >> 3, c8 = id & 7;
            int sw = r * 128 + ((c8 ^ (r & 7)) << 4);
            cp16(Ab + sw, A + (size_t)(m0 + r) * Kd + kc + c8 * 8);
            cp16(Bb + sw, B + (size_t)(n0 + r) * Kd + kc + c8 * 8);
        }
        cpc();
    };
    load(0, 0);
    if (nc > 1) load(1, 64);
    for (int i = 0; i < nc; i++) {
        if (i + 1 < nc) asm volatile("cp.async.wait_group 1;\n" ::: "memory");
        else asm volatile("cp.async.wait_group 0;\n" ::: "memory");
        __syncthreads();
        if (i + 2 < nc) load((i + 2) % STG, (i + 2) * 64);
        const char* Ab = smc + (i % STG) * STAGE_B;
        const char* Bb = Ab + 16384;
#pragma unroll
        for (int s4 = 0; s4 < 4; s4++) {
            const int ks = (((s4 + ((w & 1) << 1)) & 3) << 4);  // odd warps rotated by 32
            uint32_t af[4][4], bf[2][4];
#pragma unroll
            for (int mt = 0; mt < 4; mt++) {
                int row = mi * 64 + mt * 16 + (l & 15);
                int g = (ks >> 3) + (l >> 4);
                ldsm4(af[mt], su32(Ab + row * 128 + ((g ^ (row & 7)) << 4)));
            }
#pragma unroll
            for (int np = 0; np < 2; np++) {
                int row = ni * 32 + np * 16 + (l & 7) + ((l >> 4) << 3);
                int g = (ks >> 3) + ((l >> 3) & 1);
                ldsm4(bf[np], su32(Bb + row * 128 + ((g ^ (row & 7)) << 4)));
            }
#pragma unroll
            for (int mt = 0; mt < 4; mt++)
#pragma unroll
                for (int nt = 0; nt < 4; nt++)
                    mma(acc[mt][nt], af[mt], bf[nt >> 1][(nt & 1) << 1],
                        bf[nt >> 1][((nt & 1) << 1) + 1]);
        }
    }
    __half* sm = (__half*)smc;
    if (mode == 0) {
#pragma unroll
        for (int mt = 0; mt < 4; mt++)
#pragma unroll
            for (int nt = 0; nt < 4; nt++) {
                int gr = m0 + mi * 64 + mt * 16 + (l >> 2), gc = n0 + ni * 32 + nt * 8 + ((l & 3) << 1);
                float b0 = bias ? bias[gc] : 0.f, b1 = bias ? bias[gc + 1] : 0.f;
                __half* op = Ho + (size_t)z * sHo + (size_t)gr * ldo + gc;
                *(__half2*)op = __floats2half2_rn(fmaf(acc[mt][nt][0], scale, b0),
                                                  fmaf(acc[mt][nt][1], scale, b1));
                *(__half2*)(op + (size_t)8 * ldo) = __floats2half2_rn(
                    fmaf(acc[mt][nt][2], scale, b0), fmaf(acc[mt][nt][3], scale, b1));
            }
    } else if (mode == 1) {
        __syncthreads();
#pragma unroll
        for (int mt = 0; mt < 4; mt++)
#pragma unroll
            for (int nt = 0; nt < 4; nt++) {
                int rl = mi * 64 + mt * 16 + (l >> 2), cl = ni * 32 + nt * 8 + ((l & 3) << 1);
                float b0 = bias ? bias[n0 + cl] : 0.f, b1 = bias ? bias[n0 + cl + 1] : 0.f;
                sm[cl * 136 + rl] = __float2half(acc[mt][nt][0] + b0);
                sm[(cl + 1) * 136 + rl] = __float2half(acc[mt][nt][1] + b1);
                sm[cl * 136 + rl + 8] = __float2half(acc[mt][nt][2] + b0);
                sm[(cl + 1) * 136 + rl + 8] = __float2half(acc[mt][nt][3] + b1);
            }
        __syncthreads();
#pragma unroll
        for (int i = 0; i < 8; i++) {
            int id = i * 256 + t, r = id >> 4, mc = (id & 15) * 8;
            *(uint4*)(Ho + (size_t)z * sHo + (size_t)(n0 + r) * ldo + m0 + mc) =
                *(uint4*)(sm + r * 136 + mc);
        }
    } else {
        float* stf = (float*)smc;
        __syncthreads();
#pragma unroll
        for (int mt = 0; mt < 4; mt++)
#pragma unroll
            for (int nt = 0; nt < 4; nt++) {
                int rl = mi * 64 + mt * 16 + (l >> 2), cl = ni * 32 + nt * 8 + ((l & 3) << 1);
                float b0 = bias ? bias[n0 + cl] : 0.f, b1 = bias ? bias[n0 + cl + 1] : 0.f;
                stf[cl * 132 + rl] = acc[mt][nt][0] + b0;
                stf[(cl + 1) * 132 + rl] = acc[mt][nt][1] + b1;
                stf[cl * 132 + rl + 8] = acc[mt][nt][2] + b0;
                stf[(cl + 1) * 132 + rl + 8] = acc[mt][nt][3] + b1;
            }
        __syncthreads();
#pragma unroll
        for (int i = 0; i < 16; i++) {
            int id = i * 256 + t, r = id >> 5, mc = (id & 31) * 4;
            size_t gi = ((size_t)z * C + n0 + r) * NP + m0 + mc;
            float4 rv = *(const float4*)(res + gi);
            float4 sv = *(float4*)(stf + r * 132 + mc);
            sv.x += rv.x; sv.y += rv.y; sv.z += rv.z; sv.w += rv.w;
            *(float4*)(fo + gi) = sv;
        }
    }
}

extern "C" void kernel_launch(void* const* d_in, const int* in_sizes, int n_in, void* d_out,
                              int out_size) {
    const float* x = (const float*)d_in[0];
    const float* gw = (const float*)d_in[1];
    const float* gb = (const float*)d_in[2];
    const float* wq = (const float*)d_in[3];
    const float* bq = (const float*)d_in[4];
    const float* wk = (const float*)d_in[5];
    const float* bk = (const float*)d_in[6];
    const float* wv = (const float*)d_in[7];
    const float* bv = (const float*)d_in[8];
    const float* wp = (const float*)d_in[9];
    const float* bp = (const float*)d_in[10];
    float* out = (float*)d_out;
    __half *pH, *pQ, *pK, *pV, *pO, *pS, *pW;
    cudaGetSymbolAddress((void**)&pH, gH);
    cudaGetSymbolAddress((void**)&pQ, gQ);
    cudaGetSymbolAddress((void**)&pK, gK);
    cudaGetSymbolAddress((void**)&pV, gVt);
    cudaGetSymbolAddress((void**)&pO, gO);
    cudaGetSymbolAddress((void**)&pS, gS);
    cudaGetSymbolAddress((void**)&pW, gW);
    const int smem = STG * STAGE_B;
    cudaFuncSetAttribute(gemm, cudaFuncAttributeMaxDynamicSharedMemorySize, smem);
    cudaFuncSetAttribute(gn_apply, cudaFuncAttributeMaxDynamicSharedMemorySize, 66560);

    gn_stats<<<dim3(32, NB), 256>>>(x);
    gn_apply<<<dim3(64, NB), 256, 66560>>>(x, gw, gb);
    wconv<<<1024, 256>>>(wq, wk, wv, wp);
    const size_t sHC = (size_t)NP * C;
    // fused Q/K/V: z = batch + 8*{0:Q, 1:K, 2:V}
    gemm<<<dim3(32, 4, 24), 256, smem>>>(pH, pW, sHC, 0, 512, bq, 1.f, 0, pQ, sHC, C, nullptr,
                                         nullptr, 1, bk, bv, pK, pV);
    gemm<<<dim3(32, 32, NB), 256, smem>>>(pQ, pK, sHC, sHC, 512, nullptr, 0.044194173824159216f,
                                          0, pS, (size_t)NP * NP, NP, nullptr, nullptr, 0, nullptr,
                                          nullptr, nullptr, nullptr);
    softmax_k<<<NB * NP, 128>>>();
    gemm<<<dim3(32, 4, NB), 256, smem>>>(pS, pV, (size_t)NP * NP, sHC, 4096, nullptr, 1.f, 0, pO,
                                         sHC, C, nullptr, nullptr, 0, nullptr, nullptr, nullptr,
                                         nullptr);
    gemm<<<dim3(32, 4, NB), 256, smem>>>(pO, pW + 786432, sHC, 0, 512, bp, 1.f, 2, nullptr, 0, 0,
                                         x, out, 0, nullptr, nullptr, nullptr, nullptr);
}

// round 13
// speedup vs baseline: 1.0219x; 1.0219x over previous
#include <cuda_runtime.h>
#include <cuda_fp16.h>
#include <cstdint>
#include <cstddef>

#define DI __device__ __forceinline__
constexpr int NB = 8, C = 512, NP = 4096;

__device__ __align__(1024) __half gH[(size_t)NB * NP * C];
__device__ __align__(1024) __half gQ[(size_t)NB * NP * C];
__device__ __align__(1024) __half gK[(size_t)NB * NP * C];
__device__ __align__(1024) __half gVt[(size_t)NB * C * NP];
__device__ __align__(1024) __half gO[(size_t)NB * NP * C];
__device__ __align__(1024) __half gS[(size_t)NB * NP * NP];
__device__ __align__(1024) __half gW[4 * 512 * 512];

DI uint32_t su32(const void* p) { return (uint32_t)__cvta_generic_to_shared(p); }
DI void cp16(void* s, const void* g) {
    asm volatile("cp.async.cg.shared.global [%0], [%1], 16;\n" ::"r"(su32(s)), "l"(g) : "memory");
}
DI void cpc() { asm volatile("cp.async.commit_group;\n" ::: "memory"); }
DI void ldsm4(uint32_t* r, uint32_t a) {
    asm volatile("ldmatrix.sync.aligned.m8n8.x4.shared.b16 {%0,%1,%2,%3}, [%4];\n"
                 : "=r"(r[0]), "=r"(r[1]), "=r"(r[2]), "=r"(r[3]) : "r"(a));
}
DI void mma(float* d, const uint32_t* a, uint32_t b0, uint32_t b1) {
    asm volatile("mma.sync.aligned.m16n8k16.row.col.f32.f16.f16.f32 "
                 "{%0,%1,%2,%3}, {%4,%5,%6,%7}, {%8,%9}, {%0,%1,%2,%3};\n"
                 : "+f"(d[0]), "+f"(d[1]), "+f"(d[2]), "+f"(d[3])
                 : "r"(a[0]), "r"(a[1]), "r"(a[2]), "r"(a[3]), "r"(b0), "r"(b1));
}

// ===== fused single-pass GroupNorm: one CTA per (group, batch) slice =====
// Reads x once (fp32), stashes slice as fp16 in smem, computes stats, writes
// normalized+transposed gH[b][p][c]. Traffic: 768 MB vs 1.28 GB for 2-pass.
constexpr int GNP = 4104;  // smem pitch in halfs (conflict-free pass-2 reads)
__global__ void __launch_bounds__(256) gn_fused(const float* __restrict__ x,
                                                const float* __restrict__ gw,
                                                const float* __restrict__ gb) {
    extern __shared__ __half xs[];  // [16][GNP]
    __shared__ float rs[8], rs2[8], stat[2], scs[16], shs[16];
    const int g = blockIdx.x, b = blockIdx.y, t = threadIdx.x;
    const float4* xp = (const float4*)(x + ((size_t)b * C + g * 16) * NP);
    float s = 0.f, s2 = 0.f;
#pragma unroll 4
    for (int i = 0; i < 64; i++) {
        int id = i * 256 + t;  // 16384 float4s = 16 c x 1024 p4
        int c = id >> 10, p4 = (id & 1023) * 4;
        float4 v = xp[id];
        s += v.x + v.y + v.z + v.w;
        s2 += v.x * v.x + v.y * v.y + v.z * v.z + v.w * v.w;
        __half2* dst = (__half2*)(xs + c * GNP + p4);
        dst[0] = __floats2half2_rn(v.x, v.y);
        dst[1] = __floats2half2_rn(v.z, v.w);
    }
#pragma unroll
    for (int o = 16; o; o >>= 1) {
        s += __shfl_xor_sync(~0u, s, o);
        s2 += __shfl_xor_sync(~0u, s2, o);
    }
    if ((t & 31) == 0) { rs[t >> 5] = s; rs2[t >> 5] = s2; }
    __syncthreads();
    if (t == 0) {
        float a = 0.f, a2 = 0.f;
        for (int i = 0; i < 8; i++) { a += rs[i]; a2 += rs2[i]; }
        const float inv = 1.f / (16.f * NP);
        float m = a * inv, var = a2 * inv - m * m;
        stat[0] = m;
        stat[1] = rsqrtf(var + 1e-6f);
    }
    __syncthreads();
    if (t < 16) {
        float sc = gw[g * 16 + t] * stat[1];
        scs[t] = sc;
        shs[t] = gb[g * 16 + t] - stat[0] * sc;
    }
    __syncthreads();
    __half* dst = gH + (size_t)b * NP * C + g * 16;
#pragma unroll
    for (int grp = 0; grp < 2; grp++) {
        int p0 = grp * 2048 + t * 8;
        __half hc[16][8];
#pragma unroll
        for (int c = 0; c < 16; c++) {
            uint4 v = *(uint4*)(xs + c * GNP + p0);
            __half2* hv = (__half2*)&v;
            float sc = scs[c], sh = shs[c];
#pragma unroll
            for (int j = 0; j < 4; j++) {
                float2 f = __half22float2(hv[j]);
                hc[c][2 * j] = __float2half(fmaf(f.x, sc, sh));
                hc[c][2 * j + 1] = __float2half(fmaf(f.y, sc, sh));
            }
        }
#pragma unroll
        for (int j = 0; j < 8; j++) {
            __half o[16];
#pragma unroll
            for (int c = 0; c < 16; c++) o[c] = hc[c][j];
            uint4* op = (uint4*)(dst + (size_t)(p0 + j) * C);
            op[0] = *(uint4*)&o[0];
            op[1] = *(uint4*)&o[8];
        }
    }
}

__global__ void wconv(const float* __restrict__ wq, const float* __restrict__ wk,
                      const float* __restrict__ wv, const float* __restrict__ wp) {
    const int i = blockIdx.x * 256 + threadIdx.x;
    gW[i] = __float2half(wq[i]);
    gW[262144 + i] = __float2half(wk[i]);
    gW[524288 + i] = __float2half(wv[i]);
    gW[786432 + i] = __float2half(wp[i]);
}

__global__ void softmax_k() {
    __half* rp = gS + (size_t)blockIdx.x * NP;
    const int t = threadIdx.x;
    __half2 h[16];
    uint4* up = (uint4*)rp;
#pragma unroll
    for (int i = 0; i < 4; i++) *(uint4*)&h[i * 4] = up[i * 128 + t];
    float mx = -1e30f;
#pragma unroll
    for (int i = 0; i < 16; i++) {
        float2 f = __half22float2(h[i]);
        mx = fmaxf(mx, fmaxf(f.x, f.y));
    }
    __shared__ float sh[4], sh2[4];
#pragma unroll
    for (int o = 16; o; o >>= 1) mx = fmaxf(mx, __shfl_xor_sync(~0u, mx, o));
    if ((t & 31) == 0) sh[t >> 5] = mx;
    __syncthreads();
    mx = fmaxf(fmaxf(sh[0], sh[1]), fmaxf(sh[2], sh[3]));
    float p[32], sum = 0.f;
#pragma unroll
    for (int i = 0; i < 16; i++) {
        float2 f = __half22float2(h[i]);
        p[2 * i] = exp2f((f.x - mx) * 1.44269504f);
        p[2 * i + 1] = exp2f((f.y - mx) * 1.44269504f);
        sum += p[2 * i] + p[2 * i + 1];
    }
#pragma unroll
    for (int o = 16; o; o >>= 1) sum += __shfl_xor_sync(~0u, sum, o);
    if ((t & 31) == 0) sh2[t >> 5] = sum;
    __syncthreads();
    float inv = 1.f / (sh2[0] + sh2[1] + sh2[2] + sh2[3]);
#pragma unroll
    for (int i = 0; i < 16; i++) h[i] = __floats2half2_rn(p[2 * i] * inv, p[2 * i + 1] * inv);
#pragma unroll
    for (int i = 0; i < 4; i++) up[i * 128 + t] = *(uint4*)&h[i * 4];
}

// C[m,n] = scale*(A[m,:].B[n,:]) + bias[n];  mode 0: fp16 [m,n]; 1: fp16 [n,m]; 2: fp32 [n,m]+res
// K-chunk 64 (128B swizzled rows), 3-stage cp.async ring, warp-parity k-step stagger,
// capped at 128 regs for 2 CTAs/SM. qkv!=0: fused Q/K/V launch, z = batch + 8*weightsel.
constexpr int STG = 3;
constexpr int STAGE_B = 32768;  // A 16KB + B 16KB
__global__ void __launch_bounds__(256, 2) gemm(
    const __half* __restrict__ A, const __half* __restrict__ B, size_t sA, size_t sB, int Kd,
    const float* __restrict__ bias, float scale, int mode, __half* __restrict__ Ho, size_t sHo,
    int ldo, const float* __restrict__ res, float* __restrict__ fo, int qkv,
    const float* __restrict__ biasK, const float* __restrict__ biasV, __half* __restrict__ HoK,
    __half* __restrict__ HoV) {
    extern __shared__ __align__(1024) char smc[];
    const int m0 = blockIdx.x * 128, n0 = blockIdx.y * 128;
    int z = blockIdx.z;
    if (qkv) {
        int ws = z >> 3;
        z &= 7;
        B += (size_t)ws * 262144;
        if (ws == 1) { bias = biasK; Ho = HoK; }
        else if (ws == 2) { bias = biasV; Ho = HoV; mode = 1; ldo = NP; }
    }
    const int t = threadIdx.x, w = t >> 5, l = t & 31;
    const int mi = w >> 2, ni = w & 3;
    A += (size_t)z * sA;
    B += (size_t)z * sB;
    const int nc = Kd >> 6;
    float acc[4][4][4] = {};
    auto load = [&](int s, int kc) {
        char* Ab = smc + s * STAGE_B;
        char* Bb = Ab + 16384;
#pragma unroll
        for (int j = 0; j < 4; j++) {
            int id = t + j * 256, r = id >> 3, c8 = id & 7;
            int sw = r * 128 + ((c8 ^ (r & 7)) << 4);
            cp16(Ab + sw, A + (size_t)(m0 + r) * Kd + kc + c8 * 8);
            cp16(Bb + sw, B + (size_t)(n0 + r) * Kd + kc + c8 * 8);
        }
        cpc();
    };
    load(0, 0);
    if (nc > 1) load(1, 64);
    for (int i = 0; i < nc; i++) {
        if (i + 1 < nc) asm volatile("cp.async.wait_group 1;\n" ::: "memory");
        else asm volatile("cp.async.wait_group 0;\n" ::: "memory");
        __syncthreads();
        if (i + 2 < nc) load((i + 2) % STG, (i + 2) * 64);
        const char* Ab = smc + (i % STG) * STAGE_B;
        const char* Bb = Ab + 16384;
#pragma unroll
        for (int s4 = 0; s4 < 4; s4++) {
            const int ks = (((s4 + ((w & 1) << 1)) & 3) << 4);  // odd warps rotated by 32
            uint32_t af[4][4], bf[2][4];
#pragma unroll
            for (int mt = 0; mt < 4; mt++) {
                int row = mi * 64 + mt * 16 + (l & 15);
                int g = (ks >> 3) + (l >> 4);
                ldsm4(af[mt], su32(Ab + row * 128 + ((g ^ (row & 7)) << 4)));
            }
#pragma unroll
            for (int np = 0; np < 2; np++) {
                int row = ni * 32 + np * 16 + (l & 7) + ((l >> 4) << 3);
                int g = (ks >> 3) + ((l >> 3) & 1);
                ldsm4(bf[np], su32(Bb + row * 128 + ((g ^ (row & 7)) << 4)));
            }
#pragma unroll
            for (int mt = 0; mt < 4; mt++)
#pragma unroll
                for (int nt = 0; nt < 4; nt++)
                    mma(acc[mt][nt], af[mt], bf[nt >> 1][(nt & 1) << 1],
                        bf[nt >> 1][((nt & 1) << 1) + 1]);
        }
    }
    __half* sm = (__half*)smc;
    if (mode == 0) {
#pragma unroll
        for (int mt = 0; mt < 4; mt++)
#pragma unroll
            for (int nt = 0; nt < 4; nt++) {
                int gr = m0 + mi * 64 + mt * 16 + (l >> 2), gc = n0 + ni * 32 + nt * 8 + ((l & 3) << 1);
                float b0 = bias ? bias[gc] : 0.f, b1 = bias ? bias[gc + 1] : 0.f;
                __half* op = Ho + (size_t)z * sHo + (size_t)gr * ldo + gc;
                *(__half2*)op = __floats2half2_rn(fmaf(acc[mt][nt][0], scale, b0),
                                                  fmaf(acc[mt][nt][1], scale, b1));
                *(__half2*)(op + (size_t)8 * ldo) = __floats2half2_rn(
                    fmaf(acc[mt][nt][2], scale, b0), fmaf(acc[mt][nt][3], scale, b1));
            }
    } else if (mode == 1) {
        __syncthreads();
#pragma unroll
        for (int mt = 0; mt < 4; mt++)
#pragma unroll
            for (int nt = 0; nt < 4; nt++) {
                int rl = mi * 64 + mt * 16 + (l >> 2), cl = ni * 32 + nt * 8 + ((l & 3) << 1);
                float b0 = bias ? bias[n0 + cl] : 0.f, b1 = bias ? bias[n0 + cl + 1] : 0.f;
                sm[cl * 136 + rl] = __float2half(acc[mt][nt][0] + b0);
                sm[(cl + 1) * 136 + rl] = __float2half(acc[mt][nt][1] + b1);
                sm[cl * 136 + rl + 8] = __float2half(acc[mt][nt][2] + b0);
                sm[(cl + 1) * 136 + rl + 8] = __float2half(acc[mt][nt][3] + b1);
            }
        __syncthreads();
#pragma unroll
        for (int i = 0; i < 8; i++) {
            int id = i * 256 + t, r = id >> 4, mc = (id & 15) * 8;
            *(uint4*)(Ho + (size_t)z * sHo + (size_t)(n0 + r) * ldo + m0 + mc) =
                *(uint4*)(sm + r * 136 + mc);
        }
    } else {
        float* stf = (float*)smc;
        __syncthreads();
#pragma unroll
        for (int mt = 0; mt < 4; mt++)
#pragma unroll
            for (int nt = 0; nt < 4; nt++) {
                int rl = mi * 64 + mt * 16 + (l >> 2), cl = ni * 32 + nt * 8 + ((l & 3) << 1);
                float b0 = bias ? bias[n0 + cl] : 0.f, b1 = bias ? bias[n0 + cl + 1] : 0.f;
                stf[cl * 132 + rl] = acc[mt][nt][0] + b0;
                stf[(cl + 1) * 132 + rl] = acc[mt][nt][1] + b1;
                stf[cl * 132 + rl + 8] = acc[mt][nt][2] + b0;
                stf[(cl + 1) * 132 + rl + 8] = acc[mt][nt][3] + b1;
            }
        __syncthreads();
#pragma unroll
        for (int i = 0; i < 16; i++) {
            int id = i * 256 + t, r = id >> 5, mc = (id & 31) * 4;
            size_t gi = ((size_t)z * C + n0 + r) * NP + m0 + mc;
            float4 rv = *(const float4*)(res + gi);
            float4 sv = *(float4*)(stf + r * 132 + mc);
            sv.x += rv.x; sv.y += rv.y; sv.z += rv.z; sv.w += rv.w;
            *(float4*)(fo + gi) = sv;
        }
    }
}

extern "C" void kernel_launch(void* const* d_in, const int* in_sizes, int n_in, void* d_out,
                              int out_size) {
    const float* x = (const float*)d_in[0];
    const float* gw = (const float*)d_in[1];
    const float* gb = (const float*)d_in[2];
    const float* wq = (const float*)d_in[3];
    const float* bq = (const float*)d_in[4];
    const float* wk = (const float*)d_in[5];
    const float* bk = (const float*)d_in[6];
    const float* wv = (const float*)d_in[7];
    const float* bv = (const float*)d_in[8];
    const float* wp = (const float*)d_in[9];
    const float* bp = (const float*)d_in[10];
    float* out = (float*)d_out;
    __half *pH, *pQ, *pK, *pV, *pO, *pS, *pW;
    cudaGetSymbolAddress((void**)&pH, gH);
    cudaGetSymbolAddress((void**)&pQ, gQ);
    cudaGetSymbolAddress((void**)&pK, gK);
    cudaGetSymbolAddress((void**)&pV, gVt);
    cudaGetSymbolAddress((void**)&pO, gO);
    cudaGetSymbolAddress((void**)&pS, gS);
    cudaGetSymbolAddress((void**)&pW, gW);
    const int smem = STG * STAGE_B;
    const int gnsm = 16 * GNP * 2;  // 131328 B
    cudaFuncSetAttribute(gemm, cudaFuncAttributeMaxDynamicSharedMemorySize, smem);
    cudaFuncSetAttribute(gn_fused, cudaFuncAttributeMaxDynamicSharedMemorySize, gnsm);

    gn_fused<<<dim3(32, NB), 256, gnsm>>>(x, gw, gb);
    wconv<<<1024, 256>>>(wq, wk, wv, wp);
    const size_t sHC = (size_t)NP * C;
    // fused Q/K/V: z = batch + 8*{0:Q, 1:K, 2:V}
    gemm<<<dim3(32, 4, 24), 256, smem>>>(pH, pW, sHC, 0, 512, bq, 1.f, 0, pQ, sHC, C, nullptr,
                                         nullptr, 1, bk, bv, pK, pV);
    gemm<<<dim3(32, 32, NB), 256, smem>>>(pQ, pK, sHC, sHC, 512, nullptr, 0.044194173824159216f,
                                          0, pS, (size_t)NP * NP, NP, nullptr, nullptr, 0, nullptr,
                                          nullptr, nullptr, nullptr);
    softmax_k<<<NB * NP, 128>>>();
    gemm<<<dim3(32, 4, NB), 256, smem>>>(pS, pV, (size_t)NP * NP, sHC, 4096, nullptr, 1.f, 0, pO,
                                         sHC, C, nullptr, nullptr, 0, nullptr, nullptr, nullptr,
                                         nullptr);
    gemm<<<dim3(32, 4, NB), 256, smem>>>(pO, pW + 786432, sHC, 0, 512, bp, 1.f, 2, nullptr, 0, 0,
                                         x, out, 0, nullptr, nullptr, nullptr, nullptr);
}

// round 14
// speedup vs baseline: 1.0813x; 1.0582x over previous
#include <cuda_runtime.h>
#include <cuda_fp16.h>
#include <cstdint>
#include <cstddef>

#define DI __device__ __forceinline__
constexpr int NB = 8, C = 512, NP = 4096;

__device__ __align__(1024) __half gH[(size_t)NB * NP * C];
__device__ __align__(1024) __half gQ[(size_t)NB * NP * C];
__device__ __align__(1024) __half gK[(size_t)NB * NP * C];
__device__ __align__(1024) __half gVt[(size_t)NB * C * NP];
__device__ __align__(1024) __half gO[(size_t)NB * NP * C];
__device__ __align__(1024) __half gS[(size_t)NB * NP * NP];
__device__ __align__(1024) __half gW[4 * 512 * 512];
__device__ float gPart[(size_t)NB * 32 * NP];  // per-(z, ytile) row partial sums
__device__ float gRSum[(size_t)NB * NP];       // reciprocal row sums

DI uint32_t su32(const void* p) { return (uint32_t)__cvta_generic_to_shared(p); }
DI void cp16(void* s, const void* g) {
    asm volatile("cp.async.cg.shared.global [%0], [%1], 16;\n" ::"r"(su32(s)), "l"(g) : "memory");
}
DI void cpc() { asm volatile("cp.async.commit_group;\n" ::: "memory"); }
DI void ldsm4(uint32_t* r, uint32_t a) {
    asm volatile("ldmatrix.sync.aligned.m8n8.x4.shared.b16 {%0,%1,%2,%3}, [%4];\n"
                 : "=r"(r[0]), "=r"(r[1]), "=r"(r[2]), "=r"(r[3]) : "r"(a));
}
DI void mma(float* d, const uint32_t* a, uint32_t b0, uint32_t b1) {
    asm volatile("mma.sync.aligned.m16n8k16.row.col.f32.f16.f16.f32 "
                 "{%0,%1,%2,%3}, {%4,%5,%6,%7}, {%8,%9}, {%0,%1,%2,%3};\n"
                 : "+f"(d[0]), "+f"(d[1]), "+f"(d[2]), "+f"(d[3])
                 : "r"(a[0]), "r"(a[1]), "r"(a[2]), "r"(a[3]), "r"(b0), "r"(b1));
}

// ===== fused single-pass GroupNorm =====
constexpr int GNP = 4104;
__global__ void __launch_bounds__(256) gn_fused(const float* __restrict__ x,
                                                const float* __restrict__ gw,
                                                const float* __restrict__ gb) {
    extern __shared__ __half xs[];  // [16][GNP]
    __shared__ float rs[8], rs2[8], stat[2], scs[16], shs[16];
    const int g = blockIdx.x, b = blockIdx.y, t = threadIdx.x;
    const float4* xp = (const float4*)(x + ((size_t)b * C + g * 16) * NP);
    float s = 0.f, s2 = 0.f;
#pragma unroll 4
    for (int i = 0; i < 64; i++) {
        int id = i * 256 + t;
        int c = id >> 10, p4 = (id & 1023) * 4;
        float4 v = xp[id];
        s += v.x + v.y + v.z + v.w;
        s2 += v.x * v.x + v.y * v.y + v.z * v.z + v.w * v.w;
        __half2* dst = (__half2*)(xs + c * GNP + p4);
        dst[0] = __floats2half2_rn(v.x, v.y);
        dst[1] = __floats2half2_rn(v.z, v.w);
    }
#pragma unroll
    for (int o = 16; o; o >>= 1) {
        s += __shfl_xor_sync(~0u, s, o);
        s2 += __shfl_xor_sync(~0u, s2, o);
    }
    if ((t & 31) == 0) { rs[t >> 5] = s; rs2[t >> 5] = s2; }
    __syncthreads();
    if (t == 0) {
        float a = 0.f, a2 = 0.f;
        for (int i = 0; i < 8; i++) { a += rs[i]; a2 += rs2[i]; }
        const float inv = 1.f / (16.f * NP);
        float m = a * inv, var = a2 * inv - m * m;
        stat[0] = m;
        stat[1] = rsqrtf(var + 1e-6f);
    }
    __syncthreads();
    if (t < 16) {
        float sc = gw[g * 16 + t] * stat[1];
        scs[t] = sc;
        shs[t] = gb[g * 16 + t] - stat[0] * sc;
    }
    __syncthreads();
    __half* dst = gH + (size_t)b * NP * C + g * 16;
#pragma unroll
    for (int grp = 0; grp < 2; grp++) {
        int p0 = grp * 2048 + t * 8;
        __half hc[16][8];
#pragma unroll
        for (int c = 0; c < 16; c++) {
            uint4 v = *(uint4*)(xs + c * GNP + p0);
            __half2* hv = (__half2*)&v;
            float sc = scs[c], sh = shs[c];
#pragma unroll
            for (int j = 0; j < 4; j++) {
                float2 f = __half22float2(hv[j]);
                hc[c][2 * j] = __float2half(fmaf(f.x, sc, sh));
                hc[c][2 * j + 1] = __float2half(fmaf(f.y, sc, sh));
            }
        }
#pragma unroll
        for (int j = 0; j < 8; j++) {
            __half o[16];
#pragma unroll
            for (int c = 0; c < 16; c++) o[c] = hc[c][j];
            uint4* op = (uint4*)(dst + (size_t)(p0 + j) * C);
            op[0] = *(uint4*)&o[0];
            op[1] = *(uint4*)&o[8];
        }
    }
}

__global__ void wconv(const float* __restrict__ wq, const float* __restrict__ wk,
                      const float* __restrict__ wv, const float* __restrict__ wp) {
    const int i = blockIdx.x * 256 + threadIdx.x;
    gW[i] = __float2half(wq[i]);
    gW[262144 + i] = __float2half(wk[i]);
    gW[524288 + i] = __float2half(wv[i]);
    gW[786432 + i] = __float2half(wp[i]);
}

// reciprocal row sums from per-tile partials (deterministic fixed-order reduce)
__global__ void rowsum_reduce() {
    const int r = blockIdx.x * 256 + threadIdx.x;  // 32768 rows total
    const int z = r >> 12, row = r & 4095;
    float s = 0.f;
#pragma unroll 8
    for (int yt = 0; yt < 32; yt++) s += gPart[((size_t)z * 32 + yt) * NP + row];
    gRSum[r] = 1.0f / s;
}

// C[m,n] = scale*(A[m,:].B[n,:]) + bias[n]
// mode 0: fp16 [m,n] (rSum!=null: multiply row r by rSum[z*4096+r])
// mode 1: fp16 [n,m];  mode 2: fp32 [n,m]+residual
// mode 3: fp16 [m,n] = exp2(acc*scale), accumulate row partials into rowPart
constexpr int STG = 3;
constexpr int STAGE_B = 32768;
__global__ void __launch_bounds__(256, 2) gemm(
    const __half* __restrict__ A, const __half* __restrict__ B, size_t sA, size_t sB, int Kd,
    const float* __restrict__ bias, float scale, int mode, __half* __restrict__ Ho, size_t sHo,
    int ldo, const float* __restrict__ res, float* __restrict__ fo, int qkv,
    const float* __restrict__ biasK, const float* __restrict__ biasV, __half* __restrict__ HoK,
    __half* __restrict__ HoV, float* __restrict__ rowPart, const float* __restrict__ rSum) {
    extern __shared__ __align__(1024) char smc[];
    const int m0 = blockIdx.x * 128, n0 = blockIdx.y * 128;
    int z = blockIdx.z;
    if (qkv) {
        int ws = z >> 3;
        z &= 7;
        B += (size_t)ws * 262144;
        if (ws == 1) { bias = biasK; Ho = HoK; }
        else if (ws == 2) { bias = biasV; Ho = HoV; mode = 1; ldo = NP; }
    }
    const int t = threadIdx.x, w = t >> 5, l = t & 31;
    const int mi = w >> 2, ni = w & 3;
    A += (size_t)z * sA;
    B += (size_t)z * sB;
    const int nc = Kd >> 6;
    float acc[4][4][4] = {};
    auto load = [&](int s, int kc) {
        char* Ab = smc + s * STAGE_B;
        char* Bb = Ab + 16384;
#pragma unroll
        for (int j = 0; j < 4; j++) {
            int id = t + j * 256, r = id >> 3, c8 = id & 7;
            int sw = r * 128 + ((c8 ^ (r & 7)) << 4);
            cp16(Ab + sw, A + (size_t)(m0 + r) * Kd + kc + c8 * 8);
            cp16(Bb + sw, B + (size_t)(n0 + r) * Kd + kc + c8 * 8);
        }
        cpc();
    };
    load(0, 0);
    if (nc > 1) load(1, 64);
    for (int i = 0; i < nc; i++) {
        if (i + 1 < nc) asm volatile("cp.async.wait_group 1;\n" ::: "memory");
        else asm volatile("cp.async.wait_group 0;\n" ::: "memory");
        __syncthreads();
        if (i + 2 < nc) load((i + 2) % STG, (i + 2) * 64);
        const char* Ab = smc + (i % STG) * STAGE_B;
        const char* Bb = Ab + 16384;
#pragma unroll
        for (int s4 = 0; s4 < 4; s4++) {
            const int ks = (((s4 + ((w & 1) << 1)) & 3) << 4);
            uint32_t af[4][4], bf[2][4];
#pragma unroll
            for (int mt = 0; mt < 4; mt++) {
                int row = mi * 64 + mt * 16 + (l & 15);
                int g = (ks >> 3) + (l >> 4);
                ldsm4(af[mt], su32(Ab + row * 128 + ((g ^ (row & 7)) << 4)));
            }
#pragma unroll
            for (int np = 0; np < 2; np++) {
                int row = ni * 32 + np * 16 + (l & 7) + ((l >> 4) << 3);
                int g = (ks >> 3) + ((l >> 3) & 1);
                ldsm4(bf[np], su32(Bb + row * 128 + ((g ^ (row & 7)) << 4)));
            }
#pragma unroll
            for (int mt = 0; mt < 4; mt++)
#pragma unroll
                for (int nt = 0; nt < 4; nt++)
                    mma(acc[mt][nt], af[mt], bf[nt >> 1][(nt & 1) << 1],
                        bf[nt >> 1][((nt & 1) << 1) + 1]);
        }
    }
    __half* sm = (__half*)smc;
    if (mode == 0) {
#pragma unroll
        for (int mt = 0; mt < 4; mt++) {
            int gr = m0 + mi * 64 + mt * 16 + (l >> 2);
            float s0 = scale, s1 = scale;
            if (rSum) {
                s0 = rSum[(size_t)z * NP + gr];
                s1 = rSum[(size_t)z * NP + gr + 8];
            }
#pragma unroll
            for (int nt = 0; nt < 4; nt++) {
                int gc = n0 + ni * 32 + nt * 8 + ((l & 3) << 1);
                float b0 = bias ? bias[gc] : 0.f, b1 = bias ? bias[gc + 1] : 0.f;
                __half* op = Ho + (size_t)z * sHo + (size_t)gr * ldo + gc;
                *(__half2*)op = __floats2half2_rn(fmaf(acc[mt][nt][0], s0, b0),
                                                  fmaf(acc[mt][nt][1], s0, b1));
                *(__half2*)(op + (size_t)8 * ldo) = __floats2half2_rn(
                    fmaf(acc[mt][nt][2], s1, b0), fmaf(acc[mt][nt][3], s1, b1));
            }
        }
    } else if (mode == 3) {
        float* sPart = (float*)smc;  // [4][128]
        __syncthreads();
#pragma unroll
        for (int mt = 0; mt < 4; mt++) {
            int gr = m0 + mi * 64 + mt * 16 + (l >> 2);
            float s0 = 0.f, s1 = 0.f;
#pragma unroll
            for (int nt = 0; nt < 4; nt++) {
                int gc = n0 + ni * 32 + nt * 8 + ((l & 3) << 1);
                float e0 = exp2f(acc[mt][nt][0] * scale), e1 = exp2f(acc[mt][nt][1] * scale);
                float e2 = exp2f(acc[mt][nt][2] * scale), e3 = exp2f(acc[mt][nt][3] * scale);
                __half* op = Ho + (size_t)z * sHo + (size_t)gr * ldo + gc;
                *(__half2*)op = __floats2half2_rn(e0, e1);
                *(__half2*)(op + (size_t)8 * ldo) = __floats2half2_rn(e2, e3);
                s0 += e0 + e1;
                s1 += e2 + e3;
            }
            s0 += __shfl_xor_sync(~0u, s0, 1);
            s0 += __shfl_xor_sync(~0u, s0, 2);
            s1 += __shfl_xor_sync(~0u, s1, 1);
            s1 += __shfl_xor_sync(~0u, s1, 2);
            if ((l & 3) == 0) {
                int rl = mi * 64 + mt * 16 + (l >> 2);
                sPart[ni * 128 + rl] = s0;
                sPart[ni * 128 + rl + 8] = s1;
            }
        }
        __syncthreads();
        if (t < 128) {
            float v = sPart[t] + sPart[128 + t] + sPart[256 + t] + sPart[384 + t];
            rowPart[((size_t)z * 32 + blockIdx.y) * NP + m0 + t] = v;
        }
    } else if (mode == 1) {
        __syncthreads();
#pragma unroll
        for (int mt = 0; mt < 4; mt++)
#pragma unroll
            for (int nt = 0; nt < 4; nt++) {
                int rl = mi * 64 + mt * 16 + (l >> 2), cl = ni * 32 + nt * 8 + ((l & 3) << 1);
                float b0 = bias ? bias[n0 + cl] : 0.f, b1 = bias ? bias[n0 + cl + 1] : 0.f;
                sm[cl * 136 + rl] = __float2half(acc[mt][nt][0] + b0);
                sm[(cl + 1) * 136 + rl] = __float2half(acc[mt][nt][1] + b1);
                sm[cl * 136 + rl + 8] = __float2half(acc[mt][nt][2] + b0);
                sm[(cl + 1) * 136 + rl + 8] = __float2half(acc[mt][nt][3] + b1);
            }
        __syncthreads();
#pragma unroll
        for (int i = 0; i < 8; i++) {
            int id = i * 256 + t, r = id >> 4, mc = (id & 15) * 8;
            *(uint4*)(Ho + (size_t)z * sHo + (size_t)(n0 + r) * ldo + m0 + mc) =
                *(uint4*)(sm + r * 136 + mc);
        }
    } else {
        float* stf = (float*)smc;
        __syncthreads();
#pragma unroll
        for (int mt = 0; mt < 4; mt++)
#pragma unroll
            for (int nt = 0; nt < 4; nt++) {
                int rl = mi * 64 + mt * 16 + (l >> 2), cl = ni * 32 + nt * 8 + ((l & 3) << 1);
                float b0 = bias ? bias[n0 + cl] : 0.f, b1 = bias ? bias[n0 + cl + 1] : 0.f;
                stf[cl * 132 + rl] = acc[mt][nt][0] + b0;
                stf[(cl + 1) * 132 + rl] = acc[mt][nt][1] + b1;
                stf[cl * 132 + rl + 8] = acc[mt][nt][2] + b0;
                stf[(cl + 1) * 132 + rl + 8] = acc[mt][nt][3] + b1;
            }
        __syncthreads();
#pragma unroll
        for (int i = 0; i < 16; i++) {
            int id = i * 256 + t, r = id >> 5, mc = (id & 31) * 4;
            size_t gi = ((size_t)z * C + n0 + r) * NP + m0 + mc;
            float4 rv = *(const float4*)(res + gi);
            float4 sv = *(float4*)(stf + r * 132 + mc);
            sv.x += rv.x; sv.y += rv.y; sv.z += rv.z; sv.w += rv.w;
            *(float4*)(fo + gi) = sv;
        }
    }
}

extern "C" void kernel_launch(void* const* d_in, const int* in_sizes, int n_in, void* d_out,
                              int out_size) {
    const float* x = (const float*)d_in[0];
    const float* gw = (const float*)d_in[1];
    const float* gb = (const float*)d_in[2];
    const float* wq = (const float*)d_in[3];
    const float* bq = (const float*)d_in[4];
    const float* wk = (const float*)d_in[5];
    const float* bk = (const float*)d_in[6];
    const float* wv = (const float*)d_in[7];
    const float* bv = (const float*)d_in[8];
    const float* wp = (const float*)d_in[9];
    const float* bp = (const float*)d_in[10];
    float* out = (float*)d_out;
    __half *pH, *pQ, *pK, *pV, *pO, *pS, *pW;
    float *pPart, *pRS;
    cudaGetSymbolAddress((void**)&pH, gH);
    cudaGetSymbolAddress((void**)&pQ, gQ);
    cudaGetSymbolAddress((void**)&pK, gK);
    cudaGetSymbolAddress((void**)&pV, gVt);
    cudaGetSymbolAddress((void**)&pO, gO);
    cudaGetSymbolAddress((void**)&pS, gS);
    cudaGetSymbolAddress((void**)&pW, gW);
    cudaGetSymbolAddress((void**)&pPart, gPart);
    cudaGetSymbolAddress((void**)&pRS, gRSum);
    const int smem = STG * STAGE_B;
    const int gnsm = 16 * GNP * 2;
    cudaFuncSetAttribute(gemm, cudaFuncAttributeMaxDynamicSharedMemorySize, smem);
    cudaFuncSetAttribute(gn_fused, cudaFuncAttributeMaxDynamicSharedMemorySize, gnsm);

    gn_fused<<<dim3(32, NB), 256, gnsm>>>(x, gw, gb);
    wconv<<<1024, 256>>>(wq, wk, wv, wp);
    const size_t sHC = (size_t)NP * C;
    // fused Q/K/V: z = batch + 8*{0:Q, 1:K, 2:V}
    gemm<<<dim3(32, 4, 24), 256, smem>>>(pH, pW, sHC, 0, 512, bq, 1.f, 0, pQ, sHC, C, nullptr,
                                         nullptr, 1, bk, bv, pK, pV, nullptr, nullptr);
    // scores: exp2 epilogue, scale = c^-0.5 * log2(e)
    gemm<<<dim3(32, 32, NB), 256, smem>>>(pQ, pK, sHC, sHC, 512, nullptr,
                                          0.044194173824159216f * 1.44269504088896341f, 3, pS,
                                          (size_t)NP * NP, NP, nullptr, nullptr, 0, nullptr,
                                          nullptr, nullptr, nullptr, pPart, nullptr);
    rowsum_reduce<<<128, 256>>>();
    // PV: per-row reciprocal-sum normalization in epilogue
    gemm<<<dim3(32, 4, NB), 256, smem>>>(pS, pV, (size_t)NP * NP, sHC, 4096, nullptr, 1.f, 0, pO,
                                         sHC, C, nullptr, nullptr, 0, nullptr, nullptr, nullptr,
                                         nullptr, nullptr, pRS);
    gemm<<<dim3(32, 4, NB), 256, smem>>>(pO, pW + 786432, sHC, 0, 512, bp, 1.f, 2, nullptr, 0, 0,
                                         x, out, 0, nullptr, nullptr, nullptr, nullptr, nullptr,
                                         nullptr);
}

// round 16
// speedup vs baseline: 1.0860x; 1.0044x over previous
#include <cuda_runtime.h>
#include <cuda_fp16.h>
#include <cstdint>
#include <cstddef>

#define DI __device__ __forceinline__
constexpr int NB = 8, C = 512, NP = 4096;

__device__ __align__(1024) __half gH[(size_t)NB * NP * C];
__device__ __align__(1024) __half gQ[(size_t)NB * NP * C];
__device__ __align__(1024) __half gK[(size_t)NB * NP * C];
__device__ __align__(1024) __half gVt[(size_t)NB * C * NP];
__device__ __align__(1024) __half gO[(size_t)NB * NP * C];
__device__ __align__(1024) __half gS[(size_t)NB * NP * NP];
__device__ __align__(1024) __half gW[4 * 512 * 512];
__device__ float gPart[(size_t)NB * 32 * NP];

DI uint32_t su32(const void* p) { return (uint32_t)__cvta_generic_to_shared(p); }
DI void cp16(void* s, const void* g) {
    asm volatile("cp.async.cg.shared.global [%0], [%1], 16;\n" ::"r"(su32(s)), "l"(g) : "memory");
}
DI void cpc() { asm volatile("cp.async.commit_group;\n" ::: "memory"); }
DI void ldsm4(uint32_t* r, uint32_t a) {
    asm volatile("ldmatrix.sync.aligned.m8n8.x4.shared.b16 {%0,%1,%2,%3}, [%4];\n"
                 : "=r"(r[0]), "=r"(r[1]), "=r"(r[2]), "=r"(r[3]) : "r"(a));
}
DI void mma(float* d, const uint32_t* a, uint32_t b0, uint32_t b1) {
    asm volatile("mma.sync.aligned.m16n8k16.row.col.f32.f16.f16.f32 "
                 "{%0,%1,%2,%3}, {%4,%5,%6,%7}, {%8,%9}, {%0,%1,%2,%3};\n"
                 : "+f"(d[0]), "+f"(d[1]), "+f"(d[2]), "+f"(d[3])
                 : "r"(a[0]), "r"(a[1]), "r"(a[2]), "r"(a[3]), "r"(b0), "r"(b1));
}

// ===== fused single-pass GroupNorm =====
constexpr int GNP = 4104;
__global__ void __launch_bounds__(256) gn_fused(const float* __restrict__ x,
                                                const float* __restrict__ gw,
                                                const float* __restrict__ gb) {
    extern __shared__ __half xs[];  // [16][GNP]
    __shared__ float rs[8], rs2[8], stat[2], scs[16], shs[16];
    const int g = blockIdx.x, b = blockIdx.y, t = threadIdx.x;
    const float4* xp = (const float4*)(x + ((size_t)b * C + g * 16) * NP);
    float s = 0.f, s2 = 0.f;
#pragma unroll 4
    for (int i = 0; i < 64; i++) {
        int id = i * 256 + t;
        int c = id >> 10, p4 = (id & 1023) * 4;
        float4 v = xp[id];
        s += v.x + v.y + v.z + v.w;
        s2 += v.x * v.x + v.y * v.y + v.z * v.z + v.w * v.w;
        __half2* dst = (__half2*)(xs + c * GNP + p4);
        dst[0] = __floats2half2_rn(v.x, v.y);
        dst[1] = __floats2half2_rn(v.z, v.w);
    }
#pragma unroll
    for (int o = 16; o; o >>= 1) {
        s += __shfl_xor_sync(~0u, s, o);
        s2 += __shfl_xor_sync(~0u, s2, o);
    }
    if ((t & 31) == 0) { rs[t >> 5] = s; rs2[t >> 5] = s2; }
    __syncthreads();
    if (t == 0) {
        float a = 0.f, a2 = 0.f;
        for (int i = 0; i < 8; i++) { a += rs[i]; a2 += rs2[i]; }
        const float inv = 1.f / (16.f * NP);
        float m = a * inv, var = a2 * inv - m * m;
        stat[0] = m;
        stat[1] = rsqrtf(var + 1e-6f);
    }
    __syncthreads();
    if (t < 16) {
        float sc = gw[g * 16 + t] * stat[1];
        scs[t] = sc;
        shs[t] = gb[g * 16 + t] - stat[0] * sc;
    }
    __syncthreads();
    __half* dst = gH + (size_t)b * NP * C + g * 16;
#pragma unroll
    for (int grp = 0; grp < 2; grp++) {
        int p0 = grp * 2048 + t * 8;
        __half hc[16][8];
#pragma unroll
        for (int c = 0; c < 16; c++) {
            uint4 v = *(uint4*)(xs + c * GNP + p0);
            __half2* hv = (__half2*)&v;
            float sc = scs[c], sh = shs[c];
#pragma unroll
            for (int j = 0; j < 4; j++) {
                float2 f = __half22float2(hv[j]);
                hc[c][2 * j] = __float2half(fmaf(f.x, sc, sh));
                hc[c][2 * j + 1] = __float2half(fmaf(f.y, sc, sh));
            }
        }
#pragma unroll
        for (int j = 0; j < 8; j++) {
            __half o[16];
#pragma unroll
            for (int c = 0; c < 16; c++) o[c] = hc[c][j];
            uint4* op = (uint4*)(dst + (size_t)(p0 + j) * C);
            op[0] = *(uint4*)&o[0];
            op[1] = *(uint4*)&o[8];
        }
    }
}

__global__ void wconv(const float* __restrict__ wq, const float* __restrict__ wk,
                      const float* __restrict__ wv, const float* __restrict__ wp) {
    const int i = blockIdx.x * 256 + threadIdx.x;
    gW[i] = __float2half(wq[i]);
    gW[262144 + i] = __float2half(wk[i]);
    gW[524288 + i] = __float2half(wv[i]);
    gW[786432 + i] = __float2half(wp[i]);
}

// C[m,n] = scale*(A[m,:].B[n,:]) + bias[n]
// mode 0: fp16 [m,n]; rowNorm: multiply row r by 1/sum(gPart[z][:][r]) (PV)
// mode 1: fp16 [n,m];  mode 2: fp32 [n,m]+residual
// mode 3: fp16 [m,n] = exp2(acc*scale) via ex2.f16x2, row partials into gPart
constexpr int STG = 3;
constexpr int STAGE_B = 32768;
__global__ void __launch_bounds__(256, 2) gemm(
    const __half* __restrict__ A, const __half* __restrict__ B, size_t sA, size_t sB, int Kd,
    const float* __restrict__ bias, float scale, int mode, __half* __restrict__ Ho, size_t sHo,
    int ldo, const float* __restrict__ res, float* __restrict__ fo, int qkv,
    const float* __restrict__ biasK, const float* __restrict__ biasV, __half* __restrict__ HoK,
    __half* __restrict__ HoV, int rowNorm) {
    extern __shared__ __align__(1024) char smc[];
    __shared__ float sRS[128];
    const int m0 = blockIdx.x * 128, n0 = blockIdx.y * 128;
    int z = blockIdx.z;
    if (qkv) {
        int ws = z >> 3;
        z &= 7;
        B += (size_t)ws * 262144;
        if (ws == 1) { bias = biasK; Ho = HoK; }
        else if (ws == 2) { bias = biasV; Ho = HoV; mode = 1; ldo = NP; }
    }
    const int t = threadIdx.x, w = t >> 5, l = t & 31;
    const int mi = w >> 2, ni = w & 3;
    A += (size_t)z * sA;
    B += (size_t)z * sB;
    const int nc = Kd >> 6;
    float acc[4][4][4] = {};
    auto load = [&](int s, int kc) {
        char* Ab = smc + s * STAGE_B;
        char* Bb = Ab + 16384;
#pragma unroll
        for (int j = 0; j < 4; j++) {
            int id = t + j * 256, r = id >> 3, c8 = id & 7;
            int sw = r * 128 + ((c8 ^ (r & 7)) << 4);
            cp16(Ab + sw, A + (size_t)(m0 + r) * Kd + kc + c8 * 8);
            cp16(Bb + sw, B + (size_t)(n0 + r) * Kd + kc + c8 * 8);
        }
        cpc();
    };
    load(0, 0);
    if (nc > 1) load(1, 64);
    for (int i = 0; i < nc; i++) {
        if (i + 1 < nc) asm volatile("cp.async.wait_group 1;\n" ::: "memory");
        else asm volatile("cp.async.wait_group 0;\n" ::: "memory");
        __syncthreads();
        if (i + 2 < nc) load((i + 2) % STG, (i + 2) * 64);
        const char* Ab = smc + (i % STG) * STAGE_B;
        const char* Bb = Ab + 16384;
#pragma unroll
        for (int s4 = 0; s4 < 4; s4++) {
            const int ks = (((s4 + ((w & 1) << 1)) & 3) << 4);
            uint32_t af[4][4], bf[2][4];
#pragma unroll
            for (int mt = 0; mt < 4; mt++) {
                int row = mi * 64 + mt * 16 + (l & 15);
                int g = (ks >> 3) + (l >> 4);
                ldsm4(af[mt], su32(Ab + row * 128 + ((g ^ (row & 7)) << 4)));
            }
#pragma unroll
            for (int np = 0; np < 2; np++) {
                int row = ni * 32 + np * 16 + (l & 7) + ((l >> 4) << 3);
                int g = (ks >> 3) + ((l >> 3) & 1);
                ldsm4(bf[np], su32(Bb + row * 128 + ((g ^ (row & 7)) << 4)));
            }
#pragma unroll
            for (int mt = 0; mt < 4; mt++)
#pragma unroll
                for (int nt = 0; nt < 4; nt++)
                    mma(acc[mt][nt], af[mt], bf[nt >> 1][(nt & 1) << 1],
                        bf[nt >> 1][((nt & 1) << 1) + 1]);
        }
    }
    __half* sm = (__half*)smc;
    if (mode == 0) {
        if (rowNorm) {
            // reciprocal row sums for rows m0..m0+127 (fixed-order, deterministic)
            if (t < 128) {
                float s = 0.f;
#pragma unroll 8
                for (int yt = 0; yt < 32; yt++)
                    s += gPart[((size_t)z * 32 + yt) * NP + m0 + t];
                sRS[t] = 1.0f / s;
            }
            __syncthreads();
        }
#pragma unroll
        for (int mt = 0; mt < 4; mt++) {
            int gr = m0 + mi * 64 + mt * 16 + (l >> 2);
            float s0 = scale, s1 = scale;
            if (rowNorm) {
                s0 = sRS[gr - m0];
                s1 = sRS[gr - m0 + 8];
            }
#pragma unroll
            for (int nt = 0; nt < 4; nt++) {
                int gc = n0 + ni * 32 + nt * 8 + ((l & 3) << 1);
                float b0 = bias ? bias[gc] : 0.f, b1 = bias ? bias[gc + 1] : 0.f;
                __half* op = Ho + (size_t)z * sHo + (size_t)gr * ldo + gc;
                *(__half2*)op = __floats2half2_rn(fmaf(acc[mt][nt][0], s0, b0),
                                                  fmaf(acc[mt][nt][1], s0, b1));
                *(__half2*)(op + (size_t)8 * ldo) = __floats2half2_rn(
                    fmaf(acc[mt][nt][2], s1, b0), fmaf(acc[mt][nt][3], s1, b1));
            }
        }
    } else if (mode == 3) {
        float* sPart = (float*)smc;  // [4][128]
        __syncthreads();
#pragma unroll
        for (int mt = 0; mt < 4; mt++) {
            int gr = m0 + mi * 64 + mt * 16 + (l >> 2);
            float s0 = 0.f, s1 = 0.f;
#pragma unroll
            for (int nt = 0; nt < 4; nt++) {
                int gc = n0 + ni * 32 + nt * 8 + ((l & 3) << 1);
                float a0 = acc[mt][nt][0] * scale, a1 = acc[mt][nt][1] * scale;
                float a2 = acc[mt][nt][2] * scale, a3 = acc[mt][nt][3] * scale;
                uint32_t h01, h23, e01, e23;
                asm("cvt.rn.f16x2.f32 %0, %1, %2;" : "=r"(h01) : "f"(a1), "f"(a0));
                asm("cvt.rn.f16x2.f32 %0, %1, %2;" : "=r"(h23) : "f"(a3), "f"(a2));
                asm("ex2.approx.f16x2 %0, %1;" : "=r"(e01) : "r"(h01));
                asm("ex2.approx.f16x2 %0, %1;" : "=r"(e23) : "r"(h23));
                __half* op = Ho + (size_t)z * sHo + (size_t)gr * ldo + gc;
                *(uint32_t*)op = e01;
                *(uint32_t*)(op + (size_t)8 * ldo) = e23;
                float2 f01 = __half22float2(*(__half2*)&e01);
                float2 f23 = __half22float2(*(__half2*)&e23);
                s0 += f01.x + f01.y;
                s1 += f23.x + f23.y;
            }
            s0 += __shfl_xor_sync(~0u, s0, 1);
            s0 += __shfl_xor_sync(~0u, s0, 2);
            s1 += __shfl_xor_sync(~0u, s1, 1);
            s1 += __shfl_xor_sync(~0u, s1, 2);
            if ((l & 3) == 0) {
                int rl = mi * 64 + mt * 16 + (l >> 2);
                sPart[ni * 128 + rl] = s0;
                sPart[ni * 128 + rl + 8] = s1;
            }
        }
        __syncthreads();
        if (t < 128) {
            float v = sPart[t] + sPart[128 + t] + sPart[256 + t] + sPart[384 + t];
            gPart[((size_t)z * 32 + blockIdx.y) * NP + m0 + t] = v;
        }
    } else if (mode == 1) {
        __syncthreads();
#pragma unroll
        for (int mt = 0; mt < 4; mt++)
#pragma unroll
            for (int nt = 0; nt < 4; nt++) {
                int rl = mi * 64 + mt * 16 + (l >> 2), cl = ni * 32 + nt * 8 + ((l & 3) << 1);
                float b0 = bias ? bias[n0 + cl] : 0.f, b1 = bias ? bias[n0 + cl + 1] : 0.f;
                sm[cl * 136 + rl] = __float2half(acc[mt][nt][0] + b0);
                sm[(cl + 1) * 136 + rl] = __float2half(acc[mt][nt][1] + b1);
                sm[cl * 136 + rl + 8] = __float2half(acc[mt][nt][2] + b0);
                sm[(cl + 1) * 136 + rl + 8] = __float2half(acc[mt][nt][3] + b1);
            }
        __syncthreads();
#pragma unroll
        for (int i = 0; i < 8; i++) {
            int id = i * 256 + t, r = id >> 4, mc = (id & 15) * 8;
            *(uint4*)(Ho + (size_t)z * sHo + (size_t)(n0 + r) * ldo + m0 + mc) =
                *(uint4*)(sm + r * 136 + mc);
        }
    } else {
        float* stf = (float*)smc;
        __syncthreads();
#pragma unroll
        for (int mt = 0; mt < 4; mt++)
#pragma unroll
            for (int nt = 0; nt < 4; nt++) {
                int rl = mi * 64 + mt * 16 + (l >> 2), cl = ni * 32 + nt * 8 + ((l & 3) << 1);
                float b0 = bias ? bias[n0 + cl] : 0.f, b1 = bias ? bias[n0 + cl + 1] : 0.f;
                stf[cl * 132 + rl] = acc[mt][nt][0] + b0;
                stf[(cl + 1) * 132 + rl] = acc[mt][nt][1] + b1;
                stf[cl * 132 + rl + 8] = acc[mt][nt][2] + b0;
                stf[(cl + 1) * 132 + rl + 8] = acc[mt][nt][3] + b1;
            }
        __syncthreads();
#pragma unroll
        for (int i = 0; i < 16; i++) {
            int id = i * 256 + t, r = id >> 5, mc = (id & 31) * 4;
            size_t gi = ((size_t)z * C + n0 + r) * NP + m0 + mc;
            float4 rv = *(const float4*)(res + gi);
            float4 sv = *(float4*)(stf + r * 132 + mc);
            sv.x += rv.x; sv.y += rv.y; sv.z += rv.z; sv.w += rv.w;
            *(float4*)(fo + gi) = sv;
        }
    }
}

extern "C" void kernel_launch(void* const* d_in, const int* in_sizes, int n_in, void* d_out,
                              int out_size) {
    const float* x = (const float*)d_in[0];
    const float* gw = (const float*)d_in[1];
    const float* gb = (const float*)d_in[2];
    const float* wq = (const float*)d_in[3];
    const float* bq = (const float*)d_in[4];
    const float* wk = (const float*)d_in[5];
    const float* bk = (const float*)d_in[6];
    const float* wv = (const float*)d_in[7];
    const float* bv = (const float*)d_in[8];
    const float* wp = (const float*)d_in[9];
    const float* bp = (const float*)d_in[10];
    float* out = (float*)d_out;
    __half *pH, *pQ, *pK, *pV, *pO, *pS, *pW;
    cudaGetSymbolAddress((void**)&pH, gH);
    cudaGetSymbolAddress((void**)&pQ, gQ);
    cudaGetSymbolAddress((void**)&pK, gK);
    cudaGetSymbolAddress((void**)&pV, gVt);
    cudaGetSymbolAddress((void**)&pO, gO);
    cudaGetSymbolAddress((void**)&pS, gS);
    cudaGetSymbolAddress((void**)&pW, gW);
    const int smem = STG * STAGE_B;
    const int gnsm = 16 * GNP * 2;
    cudaFuncSetAttribute(gemm, cudaFuncAttributeMaxDynamicSharedMemorySize, smem);
    cudaFuncSetAttribute(gn_fused, cudaFuncAttributeMaxDynamicSharedMemorySize, gnsm);

    gn_fused<<<dim3(32, NB), 256, gnsm>>>(x, gw, gb);
    wconv<<<1024, 256>>>(wq, wk, wv, wp);
    const size_t sHC = (size_t)NP * C;
    const float sc2 = 0.044194173824159216f * 1.44269504088896341f;
    // fused Q/K/V: z = batch + 8*{0:Q, 1:K, 2:V}
    gemm<<<dim3(32, 4, 24), 256, smem>>>(pH, pW, sHC, 0, 512, bq, 1.f, 0, pQ, sHC, C, nullptr,
                                         nullptr, 1, bk, bv, pK, pV, 0);
    // scores: exp2(f16x2) epilogue, row partials into gPart
    gemm<<<dim3(32, 32, NB), 256, smem>>>(pQ, pK, sHC, sHC, 512, nullptr, sc2, 3, pS,
                                          (size_t)NP * NP, NP, nullptr, nullptr, 0, nullptr,
                                          nullptr, nullptr, nullptr, 0);
    // PV: row normalization (1/rowsum from gPart) fused into epilogue
    gemm<<<dim3(32, 4, NB), 256, smem>>>(pS, pV, (size_t)NP * NP, sHC, 4096, nullptr, 1.f, 0, pO,
                                         sHC, C, nullptr, nullptr, 0, nullptr, nullptr, nullptr,
                                         nullptr, 1);
    gemm<<<dim3(32, 4, NB), 256, smem>>>(pO, pW + 786432, sHC, 0, 512, bp, 1.f, 2, nullptr, 0, 0,
                                         x, out, 0, nullptr, nullptr, nullptr, nullptr, 0);
}